// round 10
// baseline (speedup 1.0000x reference)
#include <cuda_runtime.h>
#include <cuda_fp16.h>
#include <cstdint>

#define B_ 32
#define H_ 128
#define W_ 128
#define N_ 1024
#define K_ 49152
#define ROWS_ 384
#define SLABS_ 37
#define NTB_ 128
#define GS  132                      // padded table row stride (floats) -> conflict-free LDS.128

__device__ float    g_gy [H_*N_];
__device__ float    g_gxn[W_*N_];
__device__ uint16_t g_xh [B_*K_];
__device__ float    g_part[SLABS_*B_*N_];
__device__ unsigned g_cnt[8];

// smem layout (bytes)
#define SM_GXN 0                     // 128*132*4 = 67584
#define SM_GY  67584                 // 11*132*4 = 5808 -> 5824
#define ACS    1568                  // A chunk stride
#define ABUF   (8*ACS)
#define SM_A   (67584+5824)          // 2 bufs * 12544
#define SM_B   (SM_A + 2*ABUF)       // 8 warps * 2 bufs * 768
#define SMEM_TOTAL (SM_B + 16*768)   // 110784

__device__ __forceinline__ uint32_t s2u(const void* p){
    return (uint32_t)__cvta_generic_to_shared(p);
}
__device__ __forceinline__ uint32_t packh2(float a, float b){
    __half2 h = __floats2half2_rn(a, b);
    return *(uint32_t*)&h;
}
__device__ __forceinline__ void ldsm_x4(uint32_t* r, uint32_t a){
    asm volatile("ldmatrix.sync.aligned.m8n8.x4.shared.b16 {%0,%1,%2,%3}, [%4];"
      : "=r"(r[0]),"=r"(r[1]),"=r"(r[2]),"=r"(r[3]) : "r"(a));
}
__device__ __forceinline__ void ldsm_x4t(uint32_t* r, uint32_t a){
    asm volatile("ldmatrix.sync.aligned.m8n8.x4.trans.shared.b16 {%0,%1,%2,%3}, [%4];"
      : "=r"(r[0]),"=r"(r[1]),"=r"(r[2]),"=r"(r[3]) : "r"(a));
}
__device__ __forceinline__ void mma_f16(float* c, const uint32_t* a, uint32_t b0, uint32_t b1){
    asm volatile("mma.sync.aligned.m16n8k16.row.col.f32.f16.f16.f32 "
      "{%0,%1,%2,%3}, {%4,%5,%6,%7}, {%8,%9}, {%0,%1,%2,%3};"
      : "+f"(c[0]),"+f"(c[1]),"+f"(c[2]),"+f"(c[3])
      : "r"(a[0]),"r"(a[1]),"r"(a[2]),"r"(a[3]),"r"(b0),"r"(b1));
}

// ---- kernel 1: prep = tables (blocks 0..1023) + x->fp16 (1024..4095) ----
__global__ void prep(const float* __restrict__ x,
                     const float* __restrict__ mu_x, const float* __restrict__ mu_y,
                     const float* __restrict__ sg_x, const float* __restrict__ sg_y)
{
    if (blockIdx.x < 1024){
        __shared__ float red[8];
        int n = blockIdx.x, i = threadIdx.x;
        float mx = mu_x[n], my = mu_y[n], isx = 1.f/sg_x[n], isy = 1.f/sg_y[n];
        float g = (float)i*(1.f/127.f);
        float tx = (g-mx)*isx, ty = (g-my)*isy;
        float vx = expf(-0.5f*tx*tx), vy = expf(-0.5f*ty*ty);
        float sx2 = vx*vx, sy2 = vy*vy;
#pragma unroll
        for (int o=16;o;o>>=1){ sx2 += __shfl_xor_sync(~0u,sx2,o); sy2 += __shfl_xor_sync(~0u,sy2,o); }
        if ((i&31)==0){ red[i>>5]=sx2; red[4+(i>>5)]=sy2; }
        __syncthreads();
        sx2 = red[0]+red[1]+red[2]+red[3]; sy2 = red[4]+red[5]+red[6]+red[7];
        float nrm = sqrtf((float)(H_*W_)/(sx2*sy2));   // C cancels
        g_gxn[i*N_+n] = vx*nrm;  g_gy[i*N_+n] = vy;
    } else {
        int i = (blockIdx.x-1024)*128 + threadIdx.x;
        float4 v = ((const float4*)x)[i];
        ((uint2*)g_xh)[i] = make_uint2(packh2(v.x,v.y), packh2(v.z,v.w));
    }
}

// ---- kernel 2: main masked fp16 MMA GEMM (convert-ahead pipeline) + fused reduce ----
__global__ __launch_bounds__(256,2) void main_kernel(const float* __restrict__ wgt,
                                                     float* __restrict__ out)
{
    extern __shared__ char smem[];
    float* gxn_s = (float*)(smem + SM_GXN);
    float* gy_s  = (float*)(smem + SM_GY);

    const int t = threadIdx.x, lane = t&31, w = t>>5;
    const int slab = blockIdx.x, ntile = blockIdx.y, nbase = ntile*NTB_;
    const int r0 = slab*ROWS_/SLABS_, rows = (slab+1)*ROWS_/SLABS_ - r0;
    const int nch = rows*8, kbase = r0*W_;

    // preload gxn [128 x 128] (stride GS) and gy rows
    for (int i = t; i < (W_*NTB_)/4; i += 256){
        int wc = i>>5, p = (i&31)*4;
        *(float4*)(gxn_s + wc*GS + p) = *(const float4*)(g_gxn + wc*N_ + nbase + p);
    }
    for (int i = t; i < rows*32; i += 256){
        int rr = i>>5, p = (i&31)*4, h = (r0+rr)&(H_-1);
        *(float4*)(gy_s + rr*GS + p) = *(const float4*)(g_gy + h*N_ + nbase + p);
    }

    const int kq = lane>>2, q = lane&3;
    const int nq = w*16 + q*4;
    const float* wbase = wgt + (size_t)nbase + nq;
    const int bA = t>>3, hA = t&7;
    const int mat = lane>>3, rowin = lane&7;
    const uint32_t aOff = (uint32_t)(((mat&1)*8 + rowin)*48 + (mat>>1)*16);
    const uint32_t bOff = aOff;
    const uint32_t smA = s2u(smem + SM_A);
    const uint32_t smBw = s2u(smem + SM_B) + w*1536;
    char* bwp = smem + SM_B + w*1536;

    float4 wa[4][2];
#define LDW(c,s) do { if ((c) < nch){ \
    const float* p_ = wbase + (size_t)(kbase + (c)*16 + kq)*N_; \
    wa[s][0] = *(const float4*)(p_); wa[s][1] = *(const float4*)(p_ + 8*N_); } } while(0)

// convert chunk cn: masked fp16 weights -> B smem buf (cn&1)
#define CONV(cn) do { \
    const int cc_ = (cn)&7, sn_ = (cn)&3, bn_ = (cn)&1; \
    const float* gx0 = gxn_s + (cc_*16 + kq)*GS + nq; \
    float4 ga = *(const float4*)gx0; \
    float4 gb = *(const float4*)(gx0 + 8*GS); \
    float4 gyv = *(const float4*)(gy_s + ((cn)>>3)*GS + nq); \
    float4 w0 = wa[sn_][0], w1 = wa[sn_][1]; \
    uint2 lo = make_uint2(packh2(w0.x*ga.x*gyv.x, w0.y*ga.y*gyv.y), \
                          packh2(w0.z*ga.z*gyv.z, w0.w*ga.w*gyv.w)); \
    uint2 hi = make_uint2(packh2(w1.x*gb.x*gyv.x, w1.y*gb.y*gyv.y), \
                          packh2(w1.z*gb.z*gyv.z, w1.w*gb.w*gyv.w)); \
    *(uint2*)(bwp + bn_*768 + kq*48 + q*8)     = lo; \
    *(uint2*)(bwp + bn_*768 + (kq+8)*48 + q*8) = hi; } while(0)

    // prologue: A group 0, weight chunks 0..3
    {
        const uint16_t* xp = g_xh + (size_t)bA*K_ + (size_t)r0*W_;
        uint4 a0 = *(const uint4*)(xp + hA*8);
        uint4 a1 = *(const uint4*)(xp + 64 + hA*8);
        *(uint4*)(smem + SM_A + (hA>>1)*ACS + bA*48 + (hA&1)*16) = a0;
        *(uint4*)(smem + SM_A + (4+(hA>>1))*ACS + bA*48 + (hA&1)*16) = a1;
    }
    LDW(0,0); LDW(1,1); LDW(2,2); LDW(3,3);

    float acc[2][2][4];
#pragma unroll
    for (int a=0;a<2;a++)
#pragma unroll
      for (int b=0;b<2;b++)
#pragma unroll
        for (int p=0;p<4;p++) acc[a][b][p] = 0.f;

    __syncthreads();           // tables + A buf0 ready
    CONV(0);                   // B chunk 0 staged ahead
    LDW(4,0);                  // refill slot 0

    int ab = 0;
    for (int g = 0; g < rows; ++g){
        const bool more = (g+1 < rows);
        uint4 av0, av1;
        if (more){
            const uint16_t* xp = g_xh + (size_t)bA*K_ + (size_t)(r0+g+1)*W_;
            av0 = *(const uint4*)(xp + hA*8);
            av1 = *(const uint4*)(xp + 64 + hA*8);
        }
#pragma unroll
        for (int cc = 0; cc < 8; ++cc){
            const int c = g*8 + cc;
            __syncwarp();     // STS of chunk c (prev iter / prologue) visible
            uint32_t A0[4], A1[4], Bv[4];
            const uint32_t aBase = smA + ab*ABUF + cc*ACS + aOff;
            ldsm_x4 (A0, aBase);
            ldsm_x4 (A1, aBase + 768);
            ldsm_x4t(Bv, smBw + (c&1)*768 + bOff);
            if (c+1 < nch) CONV(c+1);
            LDW(c+5, (c+1)&3);
            mma_f16(acc[0][0], A0, Bv[0], Bv[1]);
            mma_f16(acc[0][1], A0, Bv[2], Bv[3]);
            mma_f16(acc[1][0], A1, Bv[0], Bv[1]);
            mma_f16(acc[1][1], A1, Bv[2], Bv[3]);
        }
        if (more){
            char* ad = smem + SM_A + (ab^1)*ABUF;
            *(uint4*)(ad + (hA>>1)*ACS + bA*48 + (hA&1)*16)     = av0;
            *(uint4*)(ad + (4+(hA>>1))*ACS + bA*48 + (hA&1)*16) = av1;
        }
        __syncthreads();
        ab ^= 1;
    }
#undef LDW
#undef CONV

    // write partials (validated mapping)
    const int grp = lane>>2, tg = lane&3;
    float* pp = g_part + (size_t)slab*(B_*N_);
#pragma unroll
    for (int mt = 0; mt < 2; ++mt)
#pragma unroll
        for (int nb = 0; nb < 2; ++nb){
            int b = mt*16 + grp;
            int n = nbase + w*16 + nb*8 + tg*2;
            *(float2*)(pp + (size_t)b*N_ + n)     = make_float2(acc[mt][nb][0], acc[mt][nb][1]);
            *(float2*)(pp + (size_t)(b+8)*N_ + n) = make_float2(acc[mt][nb][2], acc[mt][nb][3]);
        }

    // fused deterministic split-K reduction (last CTA per ntile, fixed j order)
    __threadfence();
    __syncthreads();
    __shared__ unsigned s_last;
    if (t == 0) s_last = (atomicAdd(&g_cnt[ntile], 1u) == SLABS_-1u) ? 1u : 0u;
    __syncthreads();
    if (s_last){
        __threadfence();
#pragma unroll
        for (int r = 0; r < 4; ++r){
            int f = r*256 + t;
            int b = f>>5, col4 = f&31;
            const float* src = g_part + (size_t)b*N_ + nbase + col4*4;
            float4 s = make_float4(0.f,0.f,0.f,0.f);
#pragma unroll
            for (int j = 0; j < SLABS_; ++j){
                float4 v = *(const float4*)(src + (size_t)j*(B_*N_));
                s.x += v.x; s.y += v.y; s.z += v.z; s.w += v.w;
            }
            *(float4*)(out + (size_t)b*N_ + nbase + col4*4) = s;
        }
        __syncthreads();
        if (t == 0) g_cnt[ntile] = 0;
    }
}

extern "C" void kernel_launch(void* const* d_in, const int* in_sizes, int n_in,
                              void* d_out, int out_size)
{
    const float* x   = (const float*)d_in[0];
    const float* mux = (const float*)d_in[1];
    const float* muy = (const float*)d_in[2];
    const float* sx  = (const float*)d_in[3];
    const float* sy  = (const float*)d_in[4];
    const float* wgt = (const float*)d_in[5];
    cudaFuncSetAttribute(main_kernel, cudaFuncAttributeMaxDynamicSharedMemorySize, SMEM_TOTAL);
    prep<<<4096, 128>>>(x, mux, muy, sx, sy);
    main_kernel<<<dim3(SLABS_, 8), 256, SMEM_TOTAL>>>(wgt, (float*)d_out);
}

// round 11
// speedup vs baseline: 1.0004x; 1.0004x over previous
#include <cuda_runtime.h>
#include <cuda_fp16.h>
#include <cstdint>

#define B_ 32
#define H_ 128
#define W_ 128
#define N_ 1024
#define K_ 49152
#define ROWS_ 384
#define SLABS_ 37
#define NTB_ 128
#define GS  132                      // padded table row stride (floats) -> conflict-free LDS.128

__device__ float    g_gy [H_*N_];
__device__ float    g_gxn[W_*N_];
__device__ uint16_t g_xh [B_*K_];
__device__ float    g_part[SLABS_*B_*N_];
__device__ unsigned g_cnt[8];

// smem layout (bytes)
#define SM_GXN 0                     // 128*132*4 = 67584
#define SM_GY  67584                 // 11*132*4 = 5808 -> 5824
#define ACS    1568                  // A chunk stride
#define ABUF   (8*ACS)
#define SM_A   (67584+5824)          // 2 bufs * 12544
#define SM_B   (SM_A + 2*ABUF)       // 8 warps * 2 bufs * 768
#define SMEM_TOTAL (SM_B + 16*768)   // 110784

__device__ __forceinline__ uint32_t s2u(const void* p){
    return (uint32_t)__cvta_generic_to_shared(p);
}
__device__ __forceinline__ uint32_t packh2(float a, float b){
    __half2 h = __floats2half2_rn(a, b);
    return *(uint32_t*)&h;
}
__device__ __forceinline__ void ldsm_x4(uint32_t* r, uint32_t a){
    asm volatile("ldmatrix.sync.aligned.m8n8.x4.shared.b16 {%0,%1,%2,%3}, [%4];"
      : "=r"(r[0]),"=r"(r[1]),"=r"(r[2]),"=r"(r[3]) : "r"(a));
}
__device__ __forceinline__ void ldsm_x4t(uint32_t* r, uint32_t a){
    asm volatile("ldmatrix.sync.aligned.m8n8.x4.trans.shared.b16 {%0,%1,%2,%3}, [%4];"
      : "=r"(r[0]),"=r"(r[1]),"=r"(r[2]),"=r"(r[3]) : "r"(a));
}
__device__ __forceinline__ void mma_f16(float* c, const uint32_t* a, uint32_t b0, uint32_t b1){
    asm volatile("mma.sync.aligned.m16n8k16.row.col.f32.f16.f16.f32 "
      "{%0,%1,%2,%3}, {%4,%5,%6,%7}, {%8,%9}, {%0,%1,%2,%3};"
      : "+f"(c[0]),"+f"(c[1]),"+f"(c[2]),"+f"(c[3])
      : "r"(a[0]),"r"(a[1]),"r"(a[2]),"r"(a[3]),"r"(b0),"r"(b1));
}

// ---- kernel 1: prep = tables (blocks 0..1023) + x->fp16 (1024..4095) ----
__global__ void prep(const float* __restrict__ x,
                     const float* __restrict__ mu_x, const float* __restrict__ mu_y,
                     const float* __restrict__ sg_x, const float* __restrict__ sg_y)
{
    if (blockIdx.x < 1024){
        __shared__ float red[8];
        int n = blockIdx.x, i = threadIdx.x;
        float mx = mu_x[n], my = mu_y[n], isx = 1.f/sg_x[n], isy = 1.f/sg_y[n];
        float g = (float)i*(1.f/127.f);
        float tx = (g-mx)*isx, ty = (g-my)*isy;
        float vx = expf(-0.5f*tx*tx), vy = expf(-0.5f*ty*ty);
        float sx2 = vx*vx, sy2 = vy*vy;
#pragma unroll
        for (int o=16;o;o>>=1){ sx2 += __shfl_xor_sync(~0u,sx2,o); sy2 += __shfl_xor_sync(~0u,sy2,o); }
        if ((i&31)==0){ red[i>>5]=sx2; red[4+(i>>5)]=sy2; }
        __syncthreads();
        sx2 = red[0]+red[1]+red[2]+red[3]; sy2 = red[4]+red[5]+red[6]+red[7];
        float nrm = sqrtf((float)(H_*W_)/(sx2*sy2));   // C cancels
        g_gxn[i*N_+n] = vx*nrm;  g_gy[i*N_+n] = vy;
    } else {
        int i = (blockIdx.x-1024)*128 + threadIdx.x;
        float4 v = ((const float4*)x)[i];
        ((uint2*)g_xh)[i] = make_uint2(packh2(v.x,v.y), packh2(v.z,v.w));
    }
}

// ---- kernel 2: main masked fp16 MMA GEMM (convert-ahead pipeline) + fused reduce ----
__global__ __launch_bounds__(256,2) void main_kernel(const float* __restrict__ wgt,
                                                     float* __restrict__ out)
{
    extern __shared__ char smem[];
    float* gxn_s = (float*)(smem + SM_GXN);
    float* gy_s  = (float*)(smem + SM_GY);

    const int t = threadIdx.x, lane = t&31, w = t>>5;
    const int slab = blockIdx.x, ntile = blockIdx.y, nbase = ntile*NTB_;
    const int r0 = slab*ROWS_/SLABS_, rows = (slab+1)*ROWS_/SLABS_ - r0;
    const int nch = rows*8, kbase = r0*W_;

    // preload gxn [128 x 128] (stride GS) and gy rows
    for (int i = t; i < (W_*NTB_)/4; i += 256){
        int wc = i>>5, p = (i&31)*4;
        *(float4*)(gxn_s + wc*GS + p) = *(const float4*)(g_gxn + wc*N_ + nbase + p);
    }
    for (int i = t; i < rows*32; i += 256){
        int rr = i>>5, p = (i&31)*4, h = (r0+rr)&(H_-1);
        *(float4*)(gy_s + rr*GS + p) = *(const float4*)(g_gy + h*N_ + nbase + p);
    }

    const int kq = lane>>2, q = lane&3;
    const int nq = w*16 + q*4;
    const float* wbase = wgt + (size_t)nbase + nq;
    const int bA = t>>3, hA = t&7;
    const int mat = lane>>3, rowin = lane&7;
    const uint32_t aOff = (uint32_t)(((mat&1)*8 + rowin)*48 + (mat>>1)*16);
    const uint32_t bOff = aOff;
    const uint32_t smA = s2u(smem + SM_A);
    const uint32_t smBw = s2u(smem + SM_B) + w*1536;
    char* bwp = smem + SM_B + w*1536;

    float4 wa[4][2];
#define LDW(c,s) do { if ((c) < nch){ \
    const float* p_ = wbase + (size_t)(kbase + (c)*16 + kq)*N_; \
    wa[s][0] = *(const float4*)(p_); wa[s][1] = *(const float4*)(p_ + 8*N_); } } while(0)

// convert chunk cn: masked fp16 weights -> B smem buf (cn&1)
#define CONV(cn) do { \
    const int cc_ = (cn)&7, sn_ = (cn)&3, bn_ = (cn)&1; \
    const float* gx0 = gxn_s + (cc_*16 + kq)*GS + nq; \
    float4 ga = *(const float4*)gx0; \
    float4 gb = *(const float4*)(gx0 + 8*GS); \
    float4 gyv = *(const float4*)(gy_s + ((cn)>>3)*GS + nq); \
    float4 w0 = wa[sn_][0], w1 = wa[sn_][1]; \
    uint2 lo = make_uint2(packh2(w0.x*ga.x*gyv.x, w0.y*ga.y*gyv.y), \
                          packh2(w0.z*ga.z*gyv.z, w0.w*ga.w*gyv.w)); \
    uint2 hi = make_uint2(packh2(w1.x*gb.x*gyv.x, w1.y*gb.y*gyv.y), \
                          packh2(w1.z*gb.z*gyv.z, w1.w*gb.w*gyv.w)); \
    *(uint2*)(bwp + bn_*768 + kq*48 + q*8)     = lo; \
    *(uint2*)(bwp + bn_*768 + (kq+8)*48 + q*8) = hi; } while(0)

    // prologue: A group 0, weight chunks 0..3
    {
        const uint16_t* xp = g_xh + (size_t)bA*K_ + (size_t)r0*W_;
        uint4 a0 = *(const uint4*)(xp + hA*8);
        uint4 a1 = *(const uint4*)(xp + 64 + hA*8);
        *(uint4*)(smem + SM_A + (hA>>1)*ACS + bA*48 + (hA&1)*16) = a0;
        *(uint4*)(smem + SM_A + (4+(hA>>1))*ACS + bA*48 + (hA&1)*16) = a1;
    }
    LDW(0,0); LDW(1,1); LDW(2,2); LDW(3,3);

    float acc[2][2][4];
#pragma unroll
    for (int a=0;a<2;a++)
#pragma unroll
      for (int b=0;b<2;b++)
#pragma unroll
        for (int p=0;p<4;p++) acc[a][b][p] = 0.f;

    __syncthreads();           // tables + A buf0 ready
    CONV(0);                   // B chunk 0 staged ahead
    LDW(4,0);                  // refill slot 0

    int ab = 0;
    for (int g = 0; g < rows; ++g){
        const bool more = (g+1 < rows);
        uint4 av0, av1;
        if (more){
            const uint16_t* xp = g_xh + (size_t)bA*K_ + (size_t)(r0+g+1)*W_;
            av0 = *(const uint4*)(xp + hA*8);
            av1 = *(const uint4*)(xp + 64 + hA*8);
        }
#pragma unroll
        for (int cc = 0; cc < 8; ++cc){
            const int c = g*8 + cc;
            __syncwarp();     // STS of chunk c (prev iter / prologue) visible
            uint32_t A0[4], A1[4], Bv[4];
            const uint32_t aBase = smA + ab*ABUF + cc*ACS + aOff;
            ldsm_x4 (A0, aBase);
            ldsm_x4 (A1, aBase + 768);
            ldsm_x4t(Bv, smBw + (c&1)*768 + bOff);
            if (c+1 < nch) CONV(c+1);
            LDW(c+5, (c+1)&3);
            mma_f16(acc[0][0], A0, Bv[0], Bv[1]);
            mma_f16(acc[0][1], A0, Bv[2], Bv[3]);
            mma_f16(acc[1][0], A1, Bv[0], Bv[1]);
            mma_f16(acc[1][1], A1, Bv[2], Bv[3]);
        }
        if (more){
            char* ad = smem + SM_A + (ab^1)*ABUF;
            *(uint4*)(ad + (hA>>1)*ACS + bA*48 + (hA&1)*16)     = av0;
            *(uint4*)(ad + (4+(hA>>1))*ACS + bA*48 + (hA&1)*16) = av1;
        }
        __syncthreads();
        ab ^= 1;
    }
#undef LDW
#undef CONV

    // write partials (validated mapping)
    const int grp = lane>>2, tg = lane&3;
    float* pp = g_part + (size_t)slab*(B_*N_);
#pragma unroll
    for (int mt = 0; mt < 2; ++mt)
#pragma unroll
        for (int nb = 0; nb < 2; ++nb){
            int b = mt*16 + grp;
            int n = nbase + w*16 + nb*8 + tg*2;
            *(float2*)(pp + (size_t)b*N_ + n)     = make_float2(acc[mt][nb][0], acc[mt][nb][1]);
            *(float2*)(pp + (size_t)(b+8)*N_ + n) = make_float2(acc[mt][nb][2], acc[mt][nb][3]);
        }

    // fused deterministic split-K reduction (last CTA per ntile, fixed j order)
    __threadfence();
    __syncthreads();
    __shared__ unsigned s_last;
    if (t == 0) s_last = (atomicAdd(&g_cnt[ntile], 1u) == SLABS_-1u) ? 1u : 0u;
    __syncthreads();
    if (s_last){
        __threadfence();
#pragma unroll
        for (int r = 0; r < 4; ++r){
            int f = r*256 + t;
            int b = f>>5, col4 = f&31;
            const float* src = g_part + (size_t)b*N_ + nbase + col4*4;
            float4 s = make_float4(0.f,0.f,0.f,0.f);
#pragma unroll
            for (int j = 0; j < SLABS_; ++j){
                float4 v = *(const float4*)(src + (size_t)j*(B_*N_));
                s.x += v.x; s.y += v.y; s.z += v.z; s.w += v.w;
            }
            *(float4*)(out + (size_t)b*N_ + nbase + col4*4) = s;
        }
        __syncthreads();
        if (t == 0) g_cnt[ntile] = 0;
    }
}

extern "C" void kernel_launch(void* const* d_in, const int* in_sizes, int n_in,
                              void* d_out, int out_size)
{
    const float* x   = (const float*)d_in[0];
    const float* mux = (const float*)d_in[1];
    const float* muy = (const float*)d_in[2];
    const float* sx  = (const float*)d_in[3];
    const float* sy  = (const float*)d_in[4];
    const float* wgt = (const float*)d_in[5];
    cudaFuncSetAttribute(main_kernel, cudaFuncAttributeMaxDynamicSharedMemorySize, SMEM_TOTAL);
    prep<<<4096, 128>>>(x, mux, muy, sx, sy);
    main_kernel<<<dim3(SLABS_, 8), 256, SMEM_TOTAL>>>(wgt, (float*)d_out);
}

// round 12
// speedup vs baseline: 1.2229x; 1.2225x over previous
#include <cuda_runtime.h>
#include <cuda_fp16.h>
#include <cstdint>

#define B_ 32
#define H_ 128
#define W_ 128
#define N_ 1024
#define K_ 49152
#define ROWS_ 384
#define SLABS_ 37
#define NTB_ 128

__device__ float    g_gy [H_*N_];
__device__ float    g_gxn[W_*N_];
__device__ uint16_t g_xh [B_*K_];

// smem layout (bytes) — exact R7 layout
#define SM_GXN 0                     // 65536
#define SM_GY  65536                 // 11 rows * 512 = 5632
#define ACS    1568                  // A chunk stride (32 rows * 48B + 32 pad)
#define ABUF   (8*ACS)               // 12544 per A group buffer
#define SM_A   (65536+5632)          // 2 bufs
#define SM_B   (SM_A + 2*ABUF)       // 8 warps * 2 bufs * 768B
#define SMEM_TOTAL (SM_B + 16*768)   // 108544

__device__ __forceinline__ uint32_t s2u(const void* p){
    return (uint32_t)__cvta_generic_to_shared(p);
}
__device__ __forceinline__ uint32_t packh2(float a, float b){
    __half2 h = __floats2half2_rn(a, b);
    return *(uint32_t*)&h;
}
__device__ __forceinline__ void ldsm_x4(uint32_t* r, uint32_t a){
    asm volatile("ldmatrix.sync.aligned.m8n8.x4.shared.b16 {%0,%1,%2,%3}, [%4];"
      : "=r"(r[0]),"=r"(r[1]),"=r"(r[2]),"=r"(r[3]) : "r"(a));
}
__device__ __forceinline__ void ldsm_x4t(uint32_t* r, uint32_t a){
    asm volatile("ldmatrix.sync.aligned.m8n8.x4.trans.shared.b16 {%0,%1,%2,%3}, [%4];"
      : "=r"(r[0]),"=r"(r[1]),"=r"(r[2]),"=r"(r[3]) : "r"(a));
}
__device__ __forceinline__ void mma_f16(float* c, const uint32_t* a, uint32_t b0, uint32_t b1){
    asm volatile("mma.sync.aligned.m16n8k16.row.col.f32.f16.f16.f32 "
      "{%0,%1,%2,%3}, {%4,%5,%6,%7}, {%8,%9}, {%0,%1,%2,%3};"
      : "+f"(c[0]),"+f"(c[1]),"+f"(c[2]),"+f"(c[3])
      : "r"(a[0]),"r"(a[1]),"r"(a[2]),"r"(a[3]),"r"(b0),"r"(b1));
}

// ---- kernel 1: prep = tables (blocks 0..1023, also zero out) + x->fp16 (1024..4095) ----
__global__ void prep(const float* __restrict__ x,
                     const float* __restrict__ mu_x, const float* __restrict__ mu_y,
                     const float* __restrict__ sg_x, const float* __restrict__ sg_y,
                     float* __restrict__ out)
{
    if (blockIdx.x < 1024){
        __shared__ float red[8];
        int n = blockIdx.x, i = threadIdx.x;
        // zero the output accumulator (d_out is poisoned): 8192 float4s over 1024 blocks
        if (i < 8)
            ((float4*)out)[blockIdx.x*8 + i] = make_float4(0.f,0.f,0.f,0.f);
        float mx = mu_x[n], my = mu_y[n], isx = 1.f/sg_x[n], isy = 1.f/sg_y[n];
        float g = (float)i*(1.f/127.f);
        float tx = (g-mx)*isx, ty = (g-my)*isy;
        float vx = expf(-0.5f*tx*tx), vy = expf(-0.5f*ty*ty);
        float sx2 = vx*vx, sy2 = vy*vy;
#pragma unroll
        for (int o=16;o;o>>=1){ sx2 += __shfl_xor_sync(~0u,sx2,o); sy2 += __shfl_xor_sync(~0u,sy2,o); }
        if ((i&31)==0){ red[i>>5]=sx2; red[4+(i>>5)]=sy2; }
        __syncthreads();
        sx2 = red[0]+red[1]+red[2]+red[3]; sy2 = red[4]+red[5]+red[6]+red[7];
        float nrm = sqrtf((float)(H_*W_)/(sx2*sy2));   // C cancels in normalization
        g_gxn[i*N_+n] = vx*nrm;  g_gy[i*N_+n] = vy;
    } else {
        int i = (blockIdx.x-1024)*128 + threadIdx.x;   // B*K/4 float4s
        float4 v = ((const float4*)x)[i];
        ((uint2*)g_xh)[i] = make_uint2(packh2(v.x,v.y), packh2(v.z,v.w));
    }
}

// ---- kernel 2: main masked fp16 MMA GEMM (exact R7 loop) + red-add epilogue ----
__global__ __launch_bounds__(256,2) void main_kernel(const float* __restrict__ wgt,
                                                     float* __restrict__ out)
{
    extern __shared__ char smem[];
    float* gxn_s = (float*)(smem + SM_GXN);
    float* gy_s  = (float*)(smem + SM_GY);

    const int t = threadIdx.x, lane = t&31, w = t>>5;
    const int slab = blockIdx.x, nbase = blockIdx.y*NTB_;
    const int r0 = slab*ROWS_/SLABS_, rows = (slab+1)*ROWS_/SLABS_ - r0;
    const int nch = rows*8, kbase = r0*W_;

    // preload gxn [128w x 128n] and gy rows
    for (int i = t; i < (W_*NTB_)/4; i += 256){
        int wc = i>>5, p = (i&31)*4;
        *(float4*)(gxn_s + wc*NTB_ + p) = *(const float4*)(g_gxn + wc*N_ + nbase + p);
    }
    for (int i = t; i < rows*32; i += 256){
        int rr = i>>5, p = (i&31)*4, h = (r0+rr)&(H_-1);
        *(float4*)(gy_s + rr*NTB_ + p) = *(const float4*)(g_gy + h*N_ + nbase + p);
    }

    const int kq = lane>>2, q = lane&3;
    const int nq = w*16 + q*4;
    const float* wbase = wgt + (size_t)nbase + nq;
    const int bA = t>>3, hA = t&7;
    const int mat = lane>>3, rowin = lane&7;
    const uint32_t aOff = (uint32_t)(((mat&1)*8 + rowin)*48 + (mat>>1)*16);
    const uint32_t bOff = aOff;
    const uint32_t smA = s2u(smem + SM_A);
    const uint32_t smBw = s2u(smem + SM_B) + w*1536;
    char* bwp = smem + SM_B + w*1536;

    float4 wa[4][2];
#define LDW(c,s) do { if ((c) < nch){ \
    const float* p_ = wbase + (size_t)(kbase + (c)*16 + kq)*N_; \
    wa[s][0] = *(const float4*)(p_); wa[s][1] = *(const float4*)(p_ + 8*N_); } } while(0)

    // prologue: A group 0, weight chunks 0..3
    {
        const uint16_t* xp = g_xh + (size_t)bA*K_ + (size_t)r0*W_;
        uint4 a0 = *(const uint4*)(xp + hA*8);
        uint4 a1 = *(const uint4*)(xp + 64 + hA*8);
        *(uint4*)(smem + SM_A + (hA>>1)*ACS + bA*48 + (hA&1)*16) = a0;
        *(uint4*)(smem + SM_A + (4+(hA>>1))*ACS + bA*48 + (hA&1)*16) = a1;
    }
    LDW(0,0); LDW(1,1); LDW(2,2); LDW(3,3);

    float acc[2][2][4];
#pragma unroll
    for (int a=0;a<2;a++)
#pragma unroll
      for (int b=0;b<2;b++)
#pragma unroll
        for (int p=0;p<4;p++) acc[a][b][p] = 0.f;

    __syncthreads();   // tables + A buf0 ready

    int ab = 0;
    for (int g = 0; g < rows; ++g){
        const bool more = (g+1 < rows);
        uint4 av0, av1;
        if (more){
            const uint16_t* xp = g_xh + (size_t)bA*K_ + (size_t)(r0+g+1)*W_;
            av0 = *(const uint4*)(xp + hA*8);
            av1 = *(const uint4*)(xp + 64 + hA*8);
        }
        const float4 gyv = *(const float4*)(gy_s + g*NTB_ + nq);

#pragma unroll
        for (int cc = 0; cc < 8; ++cc){
            const int c = g*8 + cc, s = c&3, bb = c&1;
            // convert 8 weights -> masked fp16, STS to private B tile
            const float* gx0 = gxn_s + (cc*16 + kq)*NTB_ + nq;
            float4 ga = *(const float4*)gx0;
            float4 gb = *(const float4*)(gx0 + 8*NTB_);
            float4 w0 = wa[s][0], w1 = wa[s][1];
            uint2 lo = make_uint2(packh2(w0.x*ga.x*gyv.x, w0.y*ga.y*gyv.y),
                                  packh2(w0.z*ga.z*gyv.z, w0.w*ga.w*gyv.w));
            uint2 hi = make_uint2(packh2(w1.x*gb.x*gyv.x, w1.y*gb.y*gyv.y),
                                  packh2(w1.z*gb.z*gyv.z, w1.w*gb.w*gyv.w));
            *(uint2*)(bwp + bb*768 + kq*48 + q*8)     = lo;
            *(uint2*)(bwp + bb*768 + (kq+8)*48 + q*8) = hi;
            LDW(c+4, s);
            __syncwarp();

            uint32_t A0[4], A1[4], Bv[4];
            const uint32_t aBase = smA + ab*ABUF + cc*ACS + aOff;
            ldsm_x4 (A0, aBase);
            ldsm_x4 (A1, aBase + 768);
            ldsm_x4t(Bv, smBw + bb*768 + bOff);
            mma_f16(acc[0][0], A0, Bv[0], Bv[1]);
            mma_f16(acc[0][1], A0, Bv[2], Bv[3]);
            mma_f16(acc[1][0], A1, Bv[0], Bv[1]);
            mma_f16(acc[1][1], A1, Bv[2], Bv[3]);
        }
        if (more){
            char* ad = smem + SM_A + (ab^1)*ABUF;
            *(uint4*)(ad + (hA>>1)*ACS + bA*48 + (hA&1)*16)     = av0;
            *(uint4*)(ad + (4+(hA>>1))*ACS + bA*48 + (hA&1)*16) = av1;
        }
        __syncthreads();
        ab ^= 1;
    }
#undef LDW

    // epilogue: direct reduction into out via red.global.add (no partials, no reduce kernel)
    const int grp = lane>>2, tg = lane&3;
#pragma unroll
    for (int mt = 0; mt < 2; ++mt)
#pragma unroll
        for (int nb = 0; nb < 2; ++nb){
            int b = mt*16 + grp;
            int n = nbase + w*16 + nb*8 + tg*2;
            atomicAdd(out + (size_t)b*N_ + n,       acc[mt][nb][0]);
            atomicAdd(out + (size_t)b*N_ + n + 1,   acc[mt][nb][1]);
            atomicAdd(out + (size_t)(b+8)*N_ + n,   acc[mt][nb][2]);
            atomicAdd(out + (size_t)(b+8)*N_ + n+1, acc[mt][nb][3]);
        }
}

extern "C" void kernel_launch(void* const* d_in, const int* in_sizes, int n_in,
                              void* d_out, int out_size)
{
    const float* x   = (const float*)d_in[0];
    const float* mux = (const float*)d_in[1];
    const float* muy = (const float*)d_in[2];
    const float* sx  = (const float*)d_in[3];
    const float* sy  = (const float*)d_in[4];
    const float* wgt = (const float*)d_in[5];
    cudaFuncSetAttribute(main_kernel, cudaFuncAttributeMaxDynamicSharedMemorySize, SMEM_TOTAL);
    prep<<<4096, 128>>>(x, mux, muy, sx, sy, (float*)d_out);
    main_kernel<<<dim3(SLABS_, 8), 256, SMEM_TOTAL>>>(wgt, (float*)d_out);
}